// round 16
// baseline (speedup 1.0000x reference)
#include <cuda_runtime.h>

#define BB 32
#define SS 2048
#define DD 1024
#define EE 16
#define KK 4
#define OO 1024
#define KD 4096
#define BS (BB*SS)

// ---------------- scratch ----------------
__device__ float g_logits[BB*EE*SS];            // [b][e][s]   4 MB
__device__ int   g_tidx[BB*EE*KK];
__device__ float g_tval[BB*EE*KK];
__device__ float g_inpT[(size_t)EE*KD*BB];      // [e][kk][m=b] 8 MB
__device__ float g_h1T[EE*OO*BB];               // [e][o][m]   2 MB
__device__ float g_h2T[EE*OO*BB];

// ---------------- helpers ----------------
union F2 { unsigned long long u; float2 f; };
union F4 { float4 v; struct { F2 lo, hi; } p; };   // float4 -> two even-aligned F2

__device__ __forceinline__ void ffma2(F2& acc, const F2& a, const F2& b) {
    asm("fma.rn.f32x2 %0, %1, %2, %0;" : "+l"(acc.u) : "l"(a.u), "l"(b.u));
}
__device__ __forceinline__ F2 fsplat(float v) {
    F2 r;
    asm("mov.b64 %0, {%1, %1};" : "=l"(r.u) : "r"(__float_as_uint(v)));
    return r;
}
__device__ __forceinline__ unsigned smem_u32(const void* p) {
    return (unsigned)__cvta_generic_to_shared(p);
}
__device__ __forceinline__ void cp_async16(unsigned dst, const void* src) {
    asm volatile("cp.async.cg.shared.global [%0], [%1], 16;" :: "r"(dst), "l"(src) : "memory");
}
__device__ __forceinline__ void cp_commit() {
    asm volatile("cp.async.commit_group;" ::: "memory");
}
__device__ __forceinline__ void cp_wait1() {
    asm volatile("cp.async.wait_group 1;" ::: "memory");
}
__device__ __forceinline__ void cp_wait3() {
    asm volatile("cp.async.wait_group 3;" ::: "memory");
}

// ---------------- K1: gate logits (R12, proven) ---------------------------
// logits[b][e][s] = x[b,s,:] . Wg[:,e]; 256 thr, 2 tokens/thread, grid 128.
// Depth-3 cp.async ring + wait1 (2-chunk lookahead). Conflict-free LDS.128
// a-reads (pitch 20) and broadcast LDS.128 wt reads (pitch 1028).
#define K1_XS_PITCH 20
#define K1_XS_BUF   (512 * K1_XS_PITCH)
#define K1_WT_PITCH 1028
#define K1_SMEM_BYTES ((3 * K1_XS_BUF + EE * K1_WT_PITCH) * 4)   // 188,672

__global__ __launch_bounds__(256) void k1_logits(const float* __restrict__ x,
                                                 const float* __restrict__ Wg) {
    extern __shared__ __align__(16) float sm[];
    float* xs = sm;                        // [3][512][20]
    float* wt = sm + 3 * K1_XS_BUF;        // [16][1028]
    const int tid  = threadIdx.x;
    const int tok0 = blockIdx.x * 512;

#pragma unroll
    for (int i = 0; i < 64; i++) {
        const int g = tid + 256 * i;       // g = d*16 + e
        wt[(g & 15) * K1_WT_PITCH + (g >> 4)] = Wg[g];
    }

    const float* xsrc[8];
    unsigned xdst[8];
#pragma unroll
    for (int i = 0; i < 8; i++) {
        const int idx = tid + 256 * i;
        const int tok = idx >> 2;
        const int c4  = (idx & 3) * 4;
        xsrc[i] = x + (size_t)(tok0 + tok) * DD + c4;
        xdst[i] = (tok * K1_XS_PITCH + c4) * 4;
    }
    const unsigned xsBase = smem_u32(xs);
    int pslot = 0;
    auto issueChunk = [&]() {
        const unsigned base = xsBase + pslot * (K1_XS_BUF * 4);
#pragma unroll
        for (int i = 0; i < 8; i++) {
            cp_async16(base + xdst[i], xsrc[i]);
            xsrc[i] += 16;
        }
        cp_commit();
        pslot = (pslot == 2) ? 0 : pslot + 1;
    };

    issueChunk();
    issueChunk();

    F2 acc[32];
#pragma unroll
    for (int i = 0; i < 32; i++) acc[i].u = 0ull;

    int cslot = 0;
    for (int dc = 0; dc < 64; dc++) {
        cp_wait1();
        __syncthreads();
        if (dc + 2 < 64) issueChunk(); else cp_commit();

        const float* a0p = xs + cslot * K1_XS_BUF + tid * K1_XS_PITCH;
        const float* a1p = a0p + 256 * K1_XS_PITCH;
        const float* wb  = wt + dc * 16;
        cslot = (cslot == 2) ? 0 : cslot + 1;
#pragma unroll
        for (int q = 0; q < 4; q++) {
            F4 a0; a0.v = *(const float4*)(a0p + q * 4);
            F4 a1; a1.v = *(const float4*)(a1p + q * 4);
#pragma unroll
            for (int e = 0; e < 16; e++) {
                F4 wq; wq.v = *(const float4*)(wb + e * K1_WT_PITCH + q * 4);
                ffma2(acc[e * 2 + 0], a0.p.lo, wq.p.lo);
                ffma2(acc[e * 2 + 0], a0.p.hi, wq.p.hi);
                ffma2(acc[e * 2 + 1], a1.p.lo, wq.p.lo);
                ffma2(acc[e * 2 + 1], a1.p.hi, wq.p.hi);
            }
        }
    }

    const int t0 = tok0 + tid;
    const int t1 = t0 + 256;
    const int b  = t0 >> 11;
    const int s0 = t0 & (SS - 1);
    const int s1 = t1 & (SS - 1);
#pragma unroll
    for (int e = 0; e < 16; e++) {
        g_logits[((size_t)(b * EE + e)) * SS + s0] = acc[e * 2 + 0].f.x + acc[e * 2 + 0].f.y;
        g_logits[((size_t)(b * EE + e)) * SS + s1] = acc[e * 2 + 1].f.x + acc[e * 2 + 1].f.y;
    }
}

// ---------------- K2: softmax stats + top-4 ------------------------------
__global__ void k2_topk() {
    const int pair = blockIdx.x * 8 + (threadIdx.x >> 5);   // b*16+e
    const int lane = threadIdx.x & 31;
    const float* __restrict__ L = g_logits + (size_t)pair * SS;

    float t0 = -3.402823466e38f, t1 = t0, t2 = t0, t3 = t0;
    int i0 = SS, i1 = SS, i2 = SS, i3 = SS;

#pragma unroll 8
    for (int s = lane; s < SS; s += 32) {
        const float v = L[s];
        if (v > t3) {
            if (v > t1) {
                if (v > t0) { t3=t2;i3=i2; t2=t1;i2=i1; t1=t0;i1=i0; t0=v;i0=s; }
                else        { t3=t2;i3=i2; t2=t1;i2=i1; t1=v;i1=s; }
            } else {
                if (v > t2) { t3=t2;i3=i2; t2=v;i2=s; }
                else        { t3=v;i3=s; }
            }
        }
    }

#pragma unroll
    for (int off = 16; off; off >>= 1) {
        float ov[4]; int oi[4];
        ov[0] = __shfl_xor_sync(0xffffffffu, t0, off); oi[0] = __shfl_xor_sync(0xffffffffu, i0, off);
        ov[1] = __shfl_xor_sync(0xffffffffu, t1, off); oi[1] = __shfl_xor_sync(0xffffffffu, i1, off);
        ov[2] = __shfl_xor_sync(0xffffffffu, t2, off); oi[2] = __shfl_xor_sync(0xffffffffu, i2, off);
        ov[3] = __shfl_xor_sync(0xffffffffu, t3, off); oi[3] = __shfl_xor_sync(0xffffffffu, i3, off);
#pragma unroll
        for (int c = 0; c < 4; c++) {
            const float v = ov[c]; const int ix = oi[c];
            const bool w3 = (v > t3) || (v == t3 && ix < i3);
            if (w3) {
                const bool w1 = (v > t1) || (v == t1 && ix < i1);
                if (w1) {
                    const bool w0 = (v > t0) || (v == t0 && ix < i0);
                    if (w0) { t3=t2;i3=i2; t2=t1;i2=i1; t1=t0;i1=i0; t0=v;i0=ix; }
                    else    { t3=t2;i3=i2; t2=t1;i2=i1; t1=v;i1=ix; }
                } else {
                    const bool w2 = (v > t2) || (v == t2 && ix < i2);
                    if (w2) { t3=t2;i3=i2; t2=v;i2=ix; }
                    else    { t3=v;i3=ix; }
                }
            }
        }
    }

    const float m = t0;
    float sum = 0.f;
#pragma unroll 8
    for (int s = lane; s < SS; s += 32) sum += expf(L[s] - m);
#pragma unroll
    for (int off = 16; off; off >>= 1) sum += __shfl_xor_sync(0xffffffffu, sum, off);

    if (lane == 0) {
        const float inv = 1.0f / sum;
        g_tidx[pair * 4 + 0] = i0; g_tval[pair * 4 + 0] = expf(t0 - m) * inv;
        g_tidx[pair * 4 + 1] = i1; g_tval[pair * 4 + 1] = expf(t1 - m) * inv;
        g_tidx[pair * 4 + 2] = i2; g_tval[pair * 4 + 2] = expf(t2 - m) * inv;
        g_tidx[pair * 4 + 3] = i3; g_tval[pair * 4 + 3] = expf(t3 - m) * inv;
    }
}

// ---------------- K4: gather+scale+TRANSPOSE into g_inpT ------------------
__global__ __launch_bounds__(256) void k4_gatherT(const float* __restrict__ x) {
    __shared__ float ts[32 * 257];
    const int t  = threadIdx.x;
    const int dc = blockIdx.x;
    const int kslot = blockIdx.y;
    const int e  = blockIdx.z;

    const int brow = t >> 3;
    const int d4   = (t & 7) * 4;
    const int idx  = g_tidx[((brow * EE + e)) * KK + kslot];
    const float val = g_tval[((brow * EE + e)) * KK + kslot];
    const float* src = x + ((size_t)brow * SS + idx) * DD + dc * 256;
#pragma unroll
    for (int i = 0; i < 8; i++) {
        const int d = d4 + 32 * i;
        const float4 v = *(const float4*)(src + d);
        float* dst = ts + brow * 257 + d;
        dst[0] = v.x * val; dst[1] = v.y * val; dst[2] = v.z * val; dst[3] = v.w * val;
    }
    __syncthreads();

    float* outb = g_inpT + (size_t)e * (KD * BB)
                + ((size_t)kslot * 1024 + dc * 256) * BB;
    const int bq = t & 7;
#pragma unroll
    for (int j = 0; j < 8; j++) {
        const int d = (t >> 3) + 32 * j;
        float4 v;
        v.x = ts[(bq * 4 + 0) * 257 + d];
        v.y = ts[(bq * 4 + 1) * 257 + d];
        v.z = ts[(bq * 4 + 2) * 257 + d];
        v.w = ts[(bq * 4 + 3) * 257 + d];
        *(float4*)(outb + (size_t)d * BB + bq * 4) = v;
    }
}

// ---------------- grouped GEMM -------------------------------------------
// CJ=8, DEPTH-5 cp.async ring, wait_group 3 -> 4 chunks (160KB) in flight
// per SM (2x R15) to raise per-SM streaming BW (MLP experiment). Producer:
// 5 cp.async16/thread/chunk from 2 base pointers. Consumer j-loop and fused
// transpose epilogue unchanged from R15.
#define CJ 8
#define NSLOT 5
#define A_SLOT (8 * CJ * 32)                       // 2048 floats
#define W_SLOT (8 * CJ * 128)                      // 8192 floats
#define RING_SLOT (A_SLOT + W_SLOT)                // 10240 floats (40KB)
#define GEMM_SMEM_BYTES (NSLOT * RING_SLOT * 4)    // 204,800

template <int KDIM>
__global__ __launch_bounds__(512) void gemm_kernel(const float* __restrict__ AT,
                                                   const float* __restrict__ W,
                                                   const float* __restrict__ bias,
                                                   float* __restrict__ Out,
                                                   float* __restrict__ OutT,
                                                   int doRelu) {
    constexpr int KPS    = KDIM / 8;
    constexpr int CHUNKS = KPS / CJ;
    static_assert(KPS % CJ == 0, "chunking");
    extern __shared__ __align__(16) float sm[];

    const int tid  = threadIdx.x;
    const int lane = tid & 31;
    const int w    = tid >> 5;
    const int rg   = w & 1;
    const int ks   = w >> 1;
    const int e    = blockIdx.y;
    const float* Ab = AT + (size_t)e * KDIM * BB;
    const float* Wb = W + (size_t)e * KDIM * OO + blockIdx.x * 128;

    // producer bases: A 1 cp/thread, W 4 cp/thread (replicas const-strided)
    const int kkA = tid >> 3;                      // 0..63 = slice(0..7)*CJ + j
    const int m4A = (tid & 7) * 4;
    const float* srcA = Ab + ((size_t)(kkA >> 3) * KPS + (kkA & 7)) * BB + m4A;
    const unsigned dstA = (unsigned)(kkA * 32 + m4A) * 4;
    const int kkW = tid >> 5;                      // 0..15
    const int c4W = (tid & 31) * 4;
    const float* srcW = Wb + ((size_t)(kkW >> 3) * KPS + (kkW & 7)) * OO + c4W;
    const unsigned dstW = (unsigned)(A_SLOT + kkW * 128 + c4W) * 4;
    const unsigned smBase = smem_u32(sm);

    int pslot = 0;
    auto issueChunk = [&]() {
        const unsigned base = smBase + pslot * (RING_SLOT * 4);
        cp_async16(base + dstA, srcA);
#pragma unroll
        for (int i = 0; i < 4; i++)                // W slices pairs: kk + 16*i
            cp_async16(base + dstW + i * (16 * 128 * 4),
                       srcW + (size_t)(2 * i) * KPS * OO);
        srcA += CJ * BB;
        srcW += CJ * OO;
        cp_commit();
        pslot = (pslot == NSLOT - 1) ? 0 : pslot + 1;
    };

    issueChunk();
    issueChunk();
    issueChunk();
    issueChunk();

    F2 acc[32];
#pragma unroll
    for (int i = 0; i < 32; i++) acc[i].u = 0ull;

    int cslot = 0;
    for (int c = 0; c < CHUNKS; c++) {
        cp_wait3();                                // chunk c resident
        __syncthreads();
        if (c + 4 < CHUNKS) issueChunk(); else cp_commit();

        const float* slot = sm + cslot * RING_SLOT;
        cslot = (cslot == NSLOT - 1) ? 0 : cslot + 1;
        const float* As = slot + (ks * CJ) * 32 + rg * 16;
        const float* Ws = slot + A_SLOT + (ks * CJ) * 128 + lane * 4;

        float4 q = *(const float4*)(Ws);           // W for j=0
#pragma unroll
        for (int j = 0; j < CJ; j++) {
            const float4 qn = (j + 1 < CJ) ? *(const float4*)(Ws + (j + 1) * 128) : q;
            const F2* ar = (const F2*)(As + j * 32);
            const F2 b0 = fsplat(q.x), b1 = fsplat(q.y),
                     b2 = fsplat(q.z), b3 = fsplat(q.w);
#pragma unroll
            for (int rp = 0; rp < 8; rp++) {
                const F2 a = ar[rp];
                ffma2(acc[rp * 4 + 0], a, b0);
                ffma2(acc[rp * 4 + 1], a, b1);
                ffma2(acc[rp * 4 + 2], a, b2);
                ffma2(acc[rp * 4 + 3], a, b3);
            }
            q = qn;
        }
    }

    // epilogue: per-rp reduce 8 K-slices via smem; write Out and/or OutT
    F2* buf = (F2*)sm;
    const int rrg = tid >> 7;              // reducer coords (tid < 256)
    const int col = tid & 127;
    const int occol = blockIdx.x * 128 + col;
    float rowv[16];

#pragma unroll
    for (int rp = 0; rp < 8; rp++) {
        __syncthreads();
#pragma unroll
        for (int c = 0; c < 4; c++)
            buf[((ks * 2 + rg) * 32 + lane) * 4 + c] = acc[rp * 4 + c];
        __syncthreads();
        if (tid < 256) {
            const int li  = col >> 2;
            const int ci  = col & 3;
            float sx = 0.f, sy = 0.f;
#pragma unroll
            for (int kss = 0; kss < 8; kss++) {
                const F2 v = buf[((kss * 2 + rrg) * 32 + li) * 4 + ci];
                sx += v.f.x; sy += v.f.y;
            }
            const float bv = bias[e * OO + occol];
            sx += bv; sy += bv;
            if (doRelu) { sx = fmaxf(sx, 0.f); sy = fmaxf(sy, 0.f); }
            if (Out) {
                const int r0 = rrg * 16 + 2 * rp;
                Out[((size_t)r0 * EE + e) * OO + occol] = sx;
                Out[((size_t)(r0 + 1) * EE + e) * OO + occol] = sy;
            }
            rowv[2 * rp]     = sx;
            rowv[2 * rp + 1] = sy;
        }
    }

    if (OutT && tid < 256) {
        float* p = OutT + ((size_t)e * OO + occol) * BB + rrg * 16;
#pragma unroll
        for (int q4 = 0; q4 < 4; q4++)
            *(float4*)(p + q4 * 4) = make_float4(rowv[q4 * 4 + 0], rowv[q4 * 4 + 1],
                                                 rowv[q4 * 4 + 2], rowv[q4 * 4 + 3]);
    }
}

// ---------------- launch ----------------
extern "C" void kernel_launch(void* const* d_in, const int* in_sizes, int n_in,
                              void* d_out, int out_size) {
    const float* x  = (const float*)d_in[0];
    const float* Wg = (const float*)d_in[1];
    // d_in[2] = bg: constant over the softmax (token) axis -> cancels exactly.
    const float* W1 = (const float*)d_in[3];
    const float* b1 = (const float*)d_in[4];
    const float* W2 = (const float*)d_in[5];
    const float* b2 = (const float*)d_in[6];
    const float* W3 = (const float*)d_in[7];
    const float* b3 = (const float*)d_in[8];
    float* out = (float*)d_out;

    void *pInpT=nullptr, *pH1T=nullptr, *pH2T=nullptr;
    cudaGetSymbolAddress(&pInpT, g_inpT);
    cudaGetSymbolAddress(&pH1T, g_h1T);
    cudaGetSymbolAddress(&pH2T, g_h2T);

    cudaFuncSetAttribute(k1_logits, cudaFuncAttributeMaxDynamicSharedMemorySize, K1_SMEM_BYTES);
    cudaFuncSetAttribute(gemm_kernel<KD>, cudaFuncAttributeMaxDynamicSharedMemorySize, GEMM_SMEM_BYTES);
    cudaFuncSetAttribute(gemm_kernel<OO>, cudaFuncAttributeMaxDynamicSharedMemorySize, GEMM_SMEM_BYTES);

    k1_logits<<<BS / 512, 256, K1_SMEM_BYTES>>>(x, Wg);
    k2_topk<<<(BB * EE) / 8, 256>>>();
    k4_gatherT<<<dim3(4, KK, EE), 256>>>(x);
    gemm_kernel<KD><<<dim3(8, EE), 512, GEMM_SMEM_BYTES>>>((const float*)pInpT, W1, b1,
                                                           nullptr, (float*)pH1T, 1);
    gemm_kernel<OO><<<dim3(8, EE), 512, GEMM_SMEM_BYTES>>>((const float*)pH1T, W2, b2,
                                                           nullptr, (float*)pH2T, 1);
    gemm_kernel<OO><<<dim3(8, EE), 512, GEMM_SMEM_BYTES>>>((const float*)pH2T, W3, b3,
                                                           out, nullptr, 0);
}

// round 17
// speedup vs baseline: 1.1040x; 1.1040x over previous
#include <cuda_runtime.h>

#define BB 32
#define SS 2048
#define DD 1024
#define EE 16
#define KK 4
#define OO 1024
#define KD 4096
#define BS (BB*SS)

// ---------------- scratch ----------------
__device__ float g_logits[BB*EE*SS];            // [b][e][s]   4 MB
__device__ int   g_tidx[BB*EE*KK];
__device__ float g_tval[BB*EE*KK];
__device__ float g_inpT[(size_t)EE*KD*BB];      // [e][kk][m=b] 8 MB
__device__ float g_h1T[EE*OO*BB];               // [e][o][m]   2 MB
__device__ float g_h2T[EE*OO*BB];

// ---------------- helpers ----------------
union F2 { unsigned long long u; float2 f; };
union F4 { float4 v; struct { F2 lo, hi; } p; };   // float4 -> two even-aligned F2

__device__ __forceinline__ void ffma2(F2& acc, const F2& a, const F2& b) {
    asm("fma.rn.f32x2 %0, %1, %2, %0;" : "+l"(acc.u) : "l"(a.u), "l"(b.u));
}
__device__ __forceinline__ F2 fsplat(float v) {
    F2 r;
    asm("mov.b64 %0, {%1, %1};" : "=l"(r.u) : "r"(__float_as_uint(v)));
    return r;
}
__device__ __forceinline__ unsigned smem_u32(const void* p) {
    return (unsigned)__cvta_generic_to_shared(p);
}
__device__ __forceinline__ void cp_async16(unsigned dst, const void* src) {
    asm volatile("cp.async.cg.shared.global [%0], [%1], 16;" :: "r"(dst), "l"(src) : "memory");
}
__device__ __forceinline__ void cp_commit() {
    asm volatile("cp.async.commit_group;" ::: "memory");
}
__device__ __forceinline__ void cp_wait0() {
    asm volatile("cp.async.wait_group 0;" ::: "memory");
}

// ---------------- K1: gate logits -----------------------------------------
// logits[b][e][s] = x[b,s,:] . Wg[:,e]; 256 thr, 2 tokens/thread, grid 128.
// R15 consumer (same per-16d work, warps, accumulation order), but chunk =
// 32 d: 32 barriers instead of 64, depth-2 ring with wait0 (chunk compute
// ~2048 cyc/SMSP >> DRAM RTT). Pitch 36 (144B rows, 16B-aligned, 36%32==4)
// -> conflict-free LDS.128 a-reads (validated R11). wt preloaded once
// (pitch 1028, broadcast LDS.128).
#define K1_XS_PITCH 36
#define K1_XS_BUF   (512 * K1_XS_PITCH)             // 18432 floats / slot
#define K1_WT_PITCH 1028
#define K1_SMEM_BYTES ((2 * K1_XS_BUF + EE * K1_WT_PITCH) * 4)   // 213,248

__global__ __launch_bounds__(256) void k1_logits(const float* __restrict__ x,
                                                 const float* __restrict__ Wg) {
    extern __shared__ __align__(16) float sm[];
    float* xs = sm;                        // [2][512][36]
    float* wt = sm + 2 * K1_XS_BUF;        // [16][1028]
    const int tid  = threadIdx.x;
    const int tok0 = blockIdx.x * 512;

    // preload all of WgT once (coalesced LDG, conflict-free STS)
#pragma unroll
    for (int i = 0; i < 64; i++) {
        const int g = tid + 256 * i;       // g = d*16 + e
        wt[(g & 15) * K1_WT_PITCH + (g >> 4)] = Wg[g];
    }

    // producer: 16 cp.async16/thread/chunk (32 d for all 512 tokens).
    // replica i: tok = tid>>3 + 32*i, c4 = (tid&7)*4 -> constant strides.
    const int ptok = tid >> 3;
    const int pc4  = (tid & 7) * 4;
    const float* xsrc = x + (size_t)(tok0 + ptok) * DD + pc4;
    const unsigned pdst = (unsigned)(ptok * K1_XS_PITCH + pc4) * 4;
    const unsigned xsBase = smem_u32(xs);
    int pslot = 0;
    auto issueChunk = [&]() {
        const unsigned base = xsBase + pslot * (K1_XS_BUF * 4) + pdst;
#pragma unroll
        for (int i = 0; i < 16; i++)
            cp_async16(base + i * (32 * K1_XS_PITCH * 4),
                       xsrc + (size_t)i * (32 * DD));
        xsrc += 32;
        cp_commit();
        pslot ^= 1;
    };

    issueChunk();

    F2 acc[32];
#pragma unroll
    for (int i = 0; i < 32; i++) acc[i].u = 0ull;

    int cslot = 0;
    for (int dc = 0; dc < 32; dc++) {      // 32-d chunks
        cp_wait0();
        __syncthreads();
        if (dc + 1 < 32) issueChunk();

        const float* a0p = xs + cslot * K1_XS_BUF + tid * K1_XS_PITCH;
        const float* a1p = a0p + 256 * K1_XS_PITCH;
        const float* wb  = wt + dc * 32;
        cslot ^= 1;
#pragma unroll
        for (int q = 0; q < 8; q++) {      // 8 x 4-d groups = 32 d
            F4 a0; a0.v = *(const float4*)(a0p + q * 4);   // conflict-free LDS.128
            F4 a1; a1.v = *(const float4*)(a1p + q * 4);
#pragma unroll
            for (int e = 0; e < 16; e++) {
                F4 wq; wq.v = *(const float4*)(wb + e * K1_WT_PITCH + q * 4); // bcast
                ffma2(acc[e * 2 + 0], a0.p.lo, wq.p.lo);
                ffma2(acc[e * 2 + 0], a0.p.hi, wq.p.hi);
                ffma2(acc[e * 2 + 1], a1.p.lo, wq.p.lo);
                ffma2(acc[e * 2 + 1], a1.p.hi, wq.p.hi);
            }
        }
    }

    const int t0 = tok0 + tid;
    const int t1 = t0 + 256;
    const int b  = t0 >> 11;               // 512 | 2048 -> same b for both
    const int s0 = t0 & (SS - 1);
    const int s1 = t1 & (SS - 1);
#pragma unroll
    for (int e = 0; e < 16; e++) {
        g_logits[((size_t)(b * EE + e)) * SS + s0] = acc[e * 2 + 0].f.x + acc[e * 2 + 0].f.y;
        g_logits[((size_t)(b * EE + e)) * SS + s1] = acc[e * 2 + 1].f.x + acc[e * 2 + 1].f.y;
    }
}

// ---------------- K2: softmax stats + top-4 ------------------------------
__global__ void k2_topk() {
    const int pair = blockIdx.x * 8 + (threadIdx.x >> 5);   // b*16+e
    const int lane = threadIdx.x & 31;
    const float* __restrict__ L = g_logits + (size_t)pair * SS;

    float t0 = -3.402823466e38f, t1 = t0, t2 = t0, t3 = t0;
    int i0 = SS, i1 = SS, i2 = SS, i3 = SS;

#pragma unroll 8
    for (int s = lane; s < SS; s += 32) {
        const float v = L[s];
        if (v > t3) {
            if (v > t1) {
                if (v > t0) { t3=t2;i3=i2; t2=t1;i2=i1; t1=t0;i1=i0; t0=v;i0=s; }
                else        { t3=t2;i3=i2; t2=t1;i2=i1; t1=v;i1=s; }
            } else {
                if (v > t2) { t3=t2;i3=i2; t2=v;i2=s; }
                else        { t3=v;i3=s; }
            }
        }
    }

#pragma unroll
    for (int off = 16; off; off >>= 1) {
        float ov[4]; int oi[4];
        ov[0] = __shfl_xor_sync(0xffffffffu, t0, off); oi[0] = __shfl_xor_sync(0xffffffffu, i0, off);
        ov[1] = __shfl_xor_sync(0xffffffffu, t1, off); oi[1] = __shfl_xor_sync(0xffffffffu, i1, off);
        ov[2] = __shfl_xor_sync(0xffffffffu, t2, off); oi[2] = __shfl_xor_sync(0xffffffffu, i2, off);
        ov[3] = __shfl_xor_sync(0xffffffffu, t3, off); oi[3] = __shfl_xor_sync(0xffffffffu, i3, off);
#pragma unroll
        for (int c = 0; c < 4; c++) {
            const float v = ov[c]; const int ix = oi[c];
            const bool w3 = (v > t3) || (v == t3 && ix < i3);
            if (w3) {
                const bool w1 = (v > t1) || (v == t1 && ix < i1);
                if (w1) {
                    const bool w0 = (v > t0) || (v == t0 && ix < i0);
                    if (w0) { t3=t2;i3=i2; t2=t1;i2=i1; t1=t0;i1=i0; t0=v;i0=ix; }
                    else    { t3=t2;i3=i2; t2=t1;i2=i1; t1=v;i1=ix; }
                } else {
                    const bool w2 = (v > t2) || (v == t2 && ix < i2);
                    if (w2) { t3=t2;i3=i2; t2=v;i2=ix; }
                    else    { t3=v;i3=ix; }
                }
            }
        }
    }

    const float m = t0;
    float sum = 0.f;
#pragma unroll 8
    for (int s = lane; s < SS; s += 32) sum += expf(L[s] - m);
#pragma unroll
    for (int off = 16; off; off >>= 1) sum += __shfl_xor_sync(0xffffffffu, sum, off);

    if (lane == 0) {
        const float inv = 1.0f / sum;
        g_tidx[pair * 4 + 0] = i0; g_tval[pair * 4 + 0] = expf(t0 - m) * inv;
        g_tidx[pair * 4 + 1] = i1; g_tval[pair * 4 + 1] = expf(t1 - m) * inv;
        g_tidx[pair * 4 + 2] = i2; g_tval[pair * 4 + 2] = expf(t2 - m) * inv;
        g_tidx[pair * 4 + 3] = i3; g_tval[pair * 4 + 3] = expf(t3 - m) * inv;
    }
}

// ---------------- K4: gather+scale+TRANSPOSE into g_inpT ------------------
__global__ __launch_bounds__(256) void k4_gatherT(const float* __restrict__ x) {
    __shared__ float ts[32 * 257];
    const int t  = threadIdx.x;
    const int dc = blockIdx.x;
    const int kslot = blockIdx.y;
    const int e  = blockIdx.z;

    const int brow = t >> 3;
    const int d4   = (t & 7) * 4;
    const int idx  = g_tidx[((brow * EE + e)) * KK + kslot];
    const float val = g_tval[((brow * EE + e)) * KK + kslot];
    const float* src = x + ((size_t)brow * SS + idx) * DD + dc * 256;
#pragma unroll
    for (int i = 0; i < 8; i++) {
        const int d = d4 + 32 * i;
        const float4 v = *(const float4*)(src + d);
        float* dst = ts + brow * 257 + d;
        dst[0] = v.x * val; dst[1] = v.y * val; dst[2] = v.z * val; dst[3] = v.w * val;
    }
    __syncthreads();

    float* outb = g_inpT + (size_t)e * (KD * BB)
                + ((size_t)kslot * 1024 + dc * 256) * BB;
    const int bq = t & 7;
#pragma unroll
    for (int j = 0; j < 8; j++) {
        const int d = (t >> 3) + 32 * j;
        float4 v;
        v.x = ts[(bq * 4 + 0) * 257 + d];
        v.y = ts[(bq * 4 + 1) * 257 + d];
        v.z = ts[(bq * 4 + 2) * 257 + d];
        v.w = ts[(bq * 4 + 3) * 257 + d];
        *(float4*)(outb + (size_t)d * BB + bq * 4) = v;
    }
}

// ---------------- grouped GEMM (R15, proven) -------------------------------
// CJ=16 depth-2 ring, W prefetch 1 j ahead. Epilogue writes Out[m][e][o]
// (final layer) or transposed hT[e][o][m] (intermediate layers).
#define CJ 16
#define A_SLOT (8 * CJ * 32)                       // 4096 floats
#define W_SLOT (8 * CJ * 128)                      // 16384 floats
#define RING_SLOT (A_SLOT + W_SLOT)                // 20480 floats
#define GEMM_SMEM_BYTES (2 * RING_SLOT * 4)        // 163,840

template <int KDIM>
__global__ __launch_bounds__(512) void gemm_kernel(const float* __restrict__ AT,
                                                   const float* __restrict__ W,
                                                   const float* __restrict__ bias,
                                                   float* __restrict__ Out,
                                                   float* __restrict__ OutT,
                                                   int doRelu) {
    constexpr int KPS    = KDIM / 8;
    constexpr int CHUNKS = KPS / CJ;
    static_assert(KPS % CJ == 0, "chunking");
    extern __shared__ __align__(16) float sm[];

    const int tid  = threadIdx.x;
    const int lane = tid & 31;
    const int w    = tid >> 5;
    const int rg   = w & 1;
    const int ks   = w >> 1;
    const int e    = blockIdx.y;
    const float* Ab = AT + (size_t)e * KDIM * BB;
    const float* Wb = W + (size_t)e * KDIM * OO + blockIdx.x * 128;

    const int kkA = tid >> 3;
    const int m4A = (tid & 7) * 4;
    const float* srcA = Ab + ((size_t)(kkA >> 4) * KPS + (kkA & 15)) * BB + m4A;
    const unsigned dstA = (unsigned)(kkA * 32 + m4A) * 4;
    const int kkW = tid >> 5;
    const int c4W = (tid & 31) * 4;
    const float* srcW = Wb + (size_t)kkW * OO + c4W;
    const unsigned dstW = (unsigned)(A_SLOT + kkW * 128 + c4W) * 4;
    const unsigned smBase = smem_u32(sm);

    int pslot = 0;
    auto issueChunk = [&]() {
        const unsigned base = smBase + pslot * (RING_SLOT * 4);
        cp_async16(base + dstA, srcA);
        cp_async16(base + dstA + 64 * 32 * 4, srcA + (size_t)4 * KPS * BB);
#pragma unroll
        for (int i = 0; i < 8; i++)
            cp_async16(base + dstW + i * (CJ * 128 * 4),
                       srcW + (size_t)i * KPS * OO);
        srcA += CJ * BB;
        srcW += CJ * OO;
        cp_commit();
        pslot ^= 1;
    };

    issueChunk();

    F2 acc[32];
#pragma unroll
    for (int i = 0; i < 32; i++) acc[i].u = 0ull;

    int cslot = 0;
    for (int c = 0; c < CHUNKS; c++) {
        cp_wait0();
        __syncthreads();
        if (c + 1 < CHUNKS) issueChunk();

        const float* slot = sm + cslot * RING_SLOT;
        cslot ^= 1;
        const float* As = slot + (ks * CJ) * 32 + rg * 16;
        const float* Ws = slot + A_SLOT + (ks * CJ) * 128 + lane * 4;

        float4 q = *(const float4*)(Ws);                  // W for j=0
#pragma unroll
        for (int j = 0; j < CJ; j++) {
            const float4 qn = (j + 1 < CJ) ? *(const float4*)(Ws + (j + 1) * 128) : q;
            const F2* ar = (const F2*)(As + j * 32);
            const F2 b0 = fsplat(q.x), b1 = fsplat(q.y),
                     b2 = fsplat(q.z), b3 = fsplat(q.w);
#pragma unroll
            for (int rp = 0; rp < 8; rp++) {
                const F2 a = ar[rp];
                ffma2(acc[rp * 4 + 0], a, b0);
                ffma2(acc[rp * 4 + 1], a, b1);
                ffma2(acc[rp * 4 + 2], a, b2);
                ffma2(acc[rp * 4 + 3], a, b3);
            }
            q = qn;
        }
    }

    // epilogue: per-rp reduce 8 K-slices via smem; write Out and/or OutT
    F2* buf = (F2*)sm;
    const int rrg = tid >> 7;              // reducer coords (tid < 256)
    const int col = tid & 127;
    const int occol = blockIdx.x * 128 + col;
    float rowv[16];

#pragma unroll
    for (int rp = 0; rp < 8; rp++) {
        __syncthreads();
#pragma unroll
        for (int c = 0; c < 4; c++)
            buf[((ks * 2 + rg) * 32 + lane) * 4 + c] = acc[rp * 4 + c];
        __syncthreads();
        if (tid < 256) {
            const int li  = col >> 2;
            const int ci  = col & 3;
            float sx = 0.f, sy = 0.f;
#pragma unroll
            for (int kss = 0; kss < 8; kss++) {
                const F2 v = buf[((kss * 2 + rrg) * 32 + li) * 4 + ci];
                sx += v.f.x; sy += v.f.y;
            }
            const float bv = bias[e * OO + occol];
            sx += bv; sy += bv;
            if (doRelu) { sx = fmaxf(sx, 0.f); sy = fmaxf(sy, 0.f); }
            if (Out) {
                const int r0 = rrg * 16 + 2 * rp;
                Out[((size_t)r0 * EE + e) * OO + occol] = sx;
                Out[((size_t)(r0 + 1) * EE + e) * OO + occol] = sy;
            }
            rowv[2 * rp]     = sx;
            rowv[2 * rp + 1] = sy;
        }
    }

    if (OutT && tid < 256) {
        float* p = OutT + ((size_t)e * OO + occol) * BB + rrg * 16;
#pragma unroll
        for (int q4 = 0; q4 < 4; q4++)
            *(float4*)(p + q4 * 4) = make_float4(rowv[q4 * 4 + 0], rowv[q4 * 4 + 1],
                                                 rowv[q4 * 4 + 2], rowv[q4 * 4 + 3]);
    }
}

// ---------------- launch ----------------
extern "C" void kernel_launch(void* const* d_in, const int* in_sizes, int n_in,
                              void* d_out, int out_size) {
    const float* x  = (const float*)d_in[0];
    const float* Wg = (const float*)d_in[1];
    // d_in[2] = bg: constant over the softmax (token) axis -> cancels exactly.
    const float* W1 = (const float*)d_in[3];
    const float* b1 = (const float*)d_in[4];
    const float* W2 = (const float*)d_in[5];
    const float* b2 = (const float*)d_in[6];
    const float* W3 = (const float*)d_in[7];
    const float* b3 = (const float*)d_in[8];
    float* out = (float*)d_out;

    void *pInpT=nullptr, *pH1T=nullptr, *pH2T=nullptr;
    cudaGetSymbolAddress(&pInpT, g_inpT);
    cudaGetSymbolAddress(&pH1T, g_h1T);
    cudaGetSymbolAddress(&pH2T, g_h2T);

    cudaFuncSetAttribute(k1_logits, cudaFuncAttributeMaxDynamicSharedMemorySize, K1_SMEM_BYTES);
    cudaFuncSetAttribute(gemm_kernel<KD>, cudaFuncAttributeMaxDynamicSharedMemorySize, GEMM_SMEM_BYTES);
    cudaFuncSetAttribute(gemm_kernel<OO>, cudaFuncAttributeMaxDynamicSharedMemorySize, GEMM_SMEM_BYTES);

    k1_logits<<<BS / 512, 256, K1_SMEM_BYTES>>>(x, Wg);
    k2_topk<<<(BB * EE) / 8, 256>>>();
    k4_gatherT<<<dim3(4, KK, EE), 256>>>(x);
    gemm_kernel<KD><<<dim3(8, EE), 512, GEMM_SMEM_BYTES>>>((const float*)pInpT, W1, b1,
                                                           nullptr, (float*)pH1T, 1);
    gemm_kernel<OO><<<dim3(8, EE), 512, GEMM_SMEM_BYTES>>>((const float*)pH1T, W2, b2,
                                                           nullptr, (float*)pH2T, 1);
    gemm_kernel<OO><<<dim3(8, EE), 512, GEMM_SMEM_BYTES>>>((const float*)pH2T, W3, b3,
                                                           out, nullptr, 0);
}